// round 12
// baseline (speedup 1.0000x reference)
#include <cuda_runtime.h>
#include <math.h>

#define ROWLEN 1152
#define PROW   1664   // padded row: l0 [0,128) | l1 @128 stride4 (slot3=dup c2) | l2 @640 stride8 (slot5=dup c4)
#define TR     4
#define NT     128

// ---------------------------------------------------------------------------
// Wigner-3j (real basis, e3nn phase convention) computed on device at launch.
// ---------------------------------------------------------------------------
__device__ float g_w3j[363];

__device__ __forceinline__ double dfact(int n) {
    double r = 1.0;
    for (int i = 2; i <= n; i++) r *= (double)i;
    return r;
}

__device__ double cg_racah(int j1, int m1, int j2, int m2, int j3, int m3) {
    if (m1 + m2 != m3) return 0.0;
    double pre = sqrt((2.0 * j3 + 1.0) * dfact(j3 + j1 - j2) * dfact(j3 - j1 + j2) *
                      dfact(j1 + j2 - j3) / dfact(j1 + j2 + j3 + 1));
    pre *= sqrt(dfact(j3 + m3) * dfact(j3 - m3) * dfact(j1 - m1) * dfact(j1 + m1) *
                dfact(j2 - m2) * dfact(j2 + m2));
    double s = 0.0;
    for (int k = 0; k <= j1 + j2 - j3; k++) {
        int d0 = k, d1 = j1 + j2 - j3 - k, d2 = j1 - m1 - k, d3 = j2 + m2 - k;
        int d4 = j3 - j2 + m1 + k, d5 = j3 - j1 - m2 + k;
        if (d0 < 0 || d1 < 0 || d2 < 0 || d3 < 0 || d4 < 0 || d5 < 0) continue;
        s += ((k & 1) ? -1.0 : 1.0) /
             (dfact(d0) * dfact(d1) * dfact(d2) * dfact(d3) * dfact(d4) * dfact(d5));
    }
    return pre * s;
}

__device__ int qrow(int l, int x, int* col, double* qre, double* qim) {
    const double s = 0.70710678118654752440;
    if (x == l) { col[0] = l; qre[0] = 1.0; qim[0] = 0.0; return 1; }
    if (x > l) {
        int m = x - l;
        col[0] = l - m; qre[0] = s;                 qim[0] = 0.0;
        col[1] = l + m; qre[1] = (m & 1) ? -s : s;  qim[1] = 0.0;
        return 2;
    }
    int m = l - x;
    col[0] = l - m; qre[0] = 0.0; qim[0] = s;
    col[1] = l + m; qre[1] = 0.0; qim[1] = (m & 1) ? s : -s;
    return 2;
}

__global__ void w3j_init_kernel() {
    __shared__ double WS[11][384];
    int t = threadIdx.x;
    if (t >= 11) return;
    const int L1[11] = {0,0,0,1,1,1,1,2,2,2,2};
    const int L2[11] = {0,1,2,0,1,1,2,0,1,2,2};
    const int L3[11] = {0,1,2,1,0,2,1,2,1,0,2};
    const int OFF[11] = {0,1,10,35,44,53,98,143,168,213,238};
    int l1 = L1[t], l2 = L2[t], l3 = L3[t];
    int d1 = 2*l1+1, d2 = 2*l2+1, d3 = 2*l3+1;
    double* Wc  = WS[t];
    double* Wre = Wc + 125;
    double* Wim = Wre + 125;
    for (int i = 0; i < 125; i++) Wc[i] = 0.0;

    for (int m1 = -l1; m1 <= l1; m1++)
        for (int m2 = -l2; m2 <= l2; m2++) {
            int m3 = -(m1 + m2);
            if (m3 < -l3 || m3 > l3) continue;
            int e = l1 - l2 - m3;
            double par = (((e % 2) + 2) % 2) ? -1.0 : 1.0;
            Wc[((m1 + l1) * d2 + (m2 + l2)) * d3 + (m3 + l3)] =
                par / sqrt(2.0 * l3 + 1.0) * cg_racah(l1, m1, l2, m2, l3, -m3);
        }

    for (int x = 0; x < d1; x++) {
        int ca[2]; double ar[2], ai[2]; int na = qrow(l1, x, ca, ar, ai);
        for (int y = 0; y < d2; y++) {
            int cb[2]; double br[2], bi[2]; int nb = qrow(l2, y, cb, br, bi);
            for (int z = 0; z < d3; z++) {
                int cc[2]; double cr[2], ci[2]; int nc = qrow(l3, z, cc, cr, ci);
                double sr = 0.0, si = 0.0;
                for (int ia = 0; ia < na; ia++)
                    for (int ib = 0; ib < nb; ib++) {
                        double pre = ar[ia]*br[ib] - ai[ia]*bi[ib];
                        double pim = ar[ia]*bi[ib] + ai[ia]*br[ib];
                        for (int ic = 0; ic < nc; ic++) {
                            double wc = Wc[(ca[ia]*d2 + cb[ib])*d3 + cc[ic]];
                            if (wc == 0.0) continue;
                            double qre = pre*cr[ic] - pim*ci[ic];
                            double qim = pre*ci[ic] + pim*cr[ic];
                            sr += qre * wc;
                            si += qim * wc;
                        }
                    }
                Wre[(x*d2 + y)*d3 + z] = sr;
                Wim[(x*d2 + y)*d3 + z] = si;
            }
        }
    }

    // Phase normalization. (2,2,2): numpy argmax tie-break lands on d0^3 (flat 62).
    int n = d1 * d2 * d3;
    int idx;
    if (l1 == 2 && l2 == 2 && l3 == 2) {
        idx = (2 * d2 + 2) * d3 + 2;
    } else {
        double M = 0.0;
        for (int i = 0; i < n; i++) {
            double h = sqrt(Wre[i]*Wre[i] + Wim[i]*Wim[i]);
            if (h > M) M = h;
        }
        idx = 0;
        for (int i = 0; i < n; i++) {
            double h = sqrt(Wre[i]*Wre[i] + Wim[i]*Wim[i]);
            if (h >= M * (1.0 - 1e-9)) { idx = i; break; }
        }
    }
    double h = sqrt(Wre[idx]*Wre[idx] + Wim[idx]*Wim[idx]);
    double pr = Wre[idx] / h, pi = Wim[idx] / h;
    for (int i = 0; i < n; i++)
        g_w3j[OFF[t] + i] = (float)(Wre[i]*pr + Wim[i]*pi);
}

// ---------------------------------------------------------------------------
// f32x2 helpers
// ---------------------------------------------------------------------------
__device__ __forceinline__ unsigned long long pack2f(float lo, float hi) {
    unsigned long long r;
    asm("mov.b64 %0, {%1, %2};" : "=l"(r) : "f"(lo), "f"(hi));
    return r;
}
__device__ __forceinline__ void ffma2(unsigned long long& d, unsigned long long a,
                                      unsigned long long b) {
    asm("fma.rn.f32x2 %0, %1, %2, %0;" : "+l"(d) : "l"(a), "l"(b));
}
__device__ __forceinline__ float2 unpack2(unsigned long long p) {
    float2 r;
    asm("mov.b64 {%0, %1}, %2;" : "=f"(r.x), "=f"(r.y) : "l"(p));
    return r;
}
union U4 { float4 q; unsigned long long p[2]; float f[4]; };
union U2 { float2 q; unsigned long long p; float f[2]; };

// Dense TP contraction, W stored with z-stride 6 (dk=5, pairs (0,1),(2,3), scalar 4).
template <int DI, int DJ>
__device__ __forceinline__ void tp_z6(const float* W, const float* cl,
                                      const float* cr, float* o, float f) {
    unsigned long long p01 = 0, p23 = 0;
    float t4 = 0.f;
#pragma unroll
    for (int x = 0; x < DI; x++)
#pragma unroll
        for (int y = 0; y < DJ; y++) {
            float pr = cl[x] * cr[y];
            unsigned long long pp = pack2f(pr, pr);
            const float* wb = W + (x * DJ + y) * 6;
            U2 w01, w23;
            w01.q = *reinterpret_cast<const float2*>(wb);
            w23.q = *reinterpret_cast<const float2*>(wb + 2);
            float w4 = wb[4];
            ffma2(p01, pp, w01.p);
            ffma2(p23, pp, w23.p);
            t4 = fmaf(pr, w4, t4);
        }
    float2 a = unpack2(p01), b = unpack2(p23);
    o[0] = fmaf(f, a.x, o[0]);
    o[1] = fmaf(f, a.y, o[1]);
    o[2] = fmaf(f, b.x, o[2]);
    o[3] = fmaf(f, b.y, o[3]);
    o[4] = fmaf(f, t4, o[4]);
}

// Dense TP contraction, W stored with z-stride 4 (dk=3, pair (0,1), scalar 2).
template <int DI, int DJ>
__device__ __forceinline__ void tp_z4(const float* W, const float* cl,
                                      const float* cr, float* o, float f) {
    unsigned long long p01 = 0;
    float t2 = 0.f;
#pragma unroll
    for (int x = 0; x < DI; x++)
#pragma unroll
        for (int y = 0; y < DJ; y++) {
            float pr = cl[x] * cr[y];
            unsigned long long pp = pack2f(pr, pr);
            const float* wb = W + (x * DJ + y) * 4;
            U2 w01;
            w01.q = *reinterpret_cast<const float2*>(wb);
            float w2 = wb[2];
            ffma2(p01, pp, w01.p);
            t2 = fmaf(pr, w2, t2);
        }
    float2 a = unpack2(p01);
    o[0] = fmaf(f, a.x, o[0]);
    o[1] = fmaf(f, a.y, o[1]);
    o[2] = fmaf(f, t2, o[2]);
}

// One-operand linear pass over A (padded layout) producing y[TR][9]. Used for linP.
__device__ __forceinline__ void linear_pass(const float* __restrict__ W,
                                            const float* A, float y[TR][9],
                                            int tid) {
    const float S = 0.08838834764831845f;  // 1/sqrt(128)
    // l=0
    {
        float a0[TR] = {0, 0, 0, 0};
#pragma unroll 2
        for (int g = 0; g < 128; g += 4) {
            float w[4];
#pragma unroll
            for (int k = 0; k < 4; k++) w[k] = __ldg(W + (g + k) * 128 + tid);
#pragma unroll
            for (int r = 0; r < TR; r++) {
                U4 xq; xq.q = *reinterpret_cast<const float4*>(&A[r * PROW + g]);
#pragma unroll
                for (int k = 0; k < 4; k++) a0[r] = fmaf(xq.f[k], w[k], a0[r]);
            }
        }
#pragma unroll
        for (int r = 0; r < TR; r++) y[r][0] = a0[r] * S;
    }
    // l=1
    {
        unsigned long long p01[TR] = {0,0,0,0}, s2[TR] = {0,0,0,0};
        const float* Wl = W + 16384;
#pragma unroll 2
        for (int g = 0; g < 128; g += 4) {
            float w[4];
#pragma unroll
            for (int k = 0; k < 4; k++) w[k] = __ldg(Wl + (g + k) * 128 + tid);
#pragma unroll
            for (int k = 0; k < 4; k++) {
                unsigned long long w2 = pack2f(w[k], w[k]);
#pragma unroll
                for (int r = 0; r < TR; r++) {
                    U4 q; q.q = *reinterpret_cast<const float4*>(
                        &A[r * PROW + 128 + (g + k) * 4]);
                    ffma2(p01[r], q.p[0], w2);
                    ffma2(s2[r], q.p[1], w2);   // both lanes accumulate c2*w
                }
            }
        }
#pragma unroll
        for (int r = 0; r < TR; r++) {
            float2 t = unpack2(p01[r]);
            y[r][1] = t.x * S; y[r][2] = t.y * S;
            y[r][3] = unpack2(s2[r]).x * S;
        }
    }
    // l=2
    {
        unsigned long long p0[TR] = {0,0,0,0}, p1[TR] = {0,0,0,0}, s4[TR] = {0,0,0,0};
        const float* Wl = W + 32768;
#pragma unroll 2
        for (int g = 0; g < 128; g += 4) {
            float w[4];
#pragma unroll
            for (int k = 0; k < 4; k++) w[k] = __ldg(Wl + (g + k) * 128 + tid);
#pragma unroll
            for (int k = 0; k < 4; k++) {
                unsigned long long w2 = pack2f(w[k], w[k]);
#pragma unroll
                for (int r = 0; r < TR; r++) {
                    const float* base = &A[r * PROW + 640 + (g + k) * 8];
                    U4 q; q.q = *reinterpret_cast<const float4*>(base);
                    U2 d; d.q = *reinterpret_cast<const float2*>(base + 4);
                    ffma2(p0[r], q.p[0], w2);
                    ffma2(p1[r], q.p[1], w2);
                    ffma2(s4[r], d.p, w2);
                }
            }
        }
#pragma unroll
        for (int r = 0; r < TR; r++) {
            float2 t = unpack2(p0[r]);
            y[r][4] = t.x * S; y[r][5] = t.y * S;
            t = unpack2(p1[r]);
            y[r][6] = t.x * S; y[r][7] = t.y * S;
            y[r][8] = unpack2(s4[r]).x * S;
        }
    }
}

// ---------------------------------------------------------------------------
// Fused main kernel. TR=4/occ4. The L and R linears are FUSED into one pass
// over the activations (halves the dominant broadcast-LDS stream); xl is
// parked into XL smem incrementally per l-block (so xl never occupies
// registers), xr accumulates gradually in registers (4 -> 16 -> 36).
// ---------------------------------------------------------------------------
__global__ __launch_bounds__(NT, 4) void self_layer_kernel(
    const float* __restrict__ x, const float* __restrict__ oldf,
    const float* __restrict__ lw, const float* __restrict__ lb,
    const float* __restrict__ rw, const float* __restrict__ rb,
    const float* __restrict__ pwm, const float* __restrict__ pb,
    const float* __restrict__ tpw, const float* __restrict__ lnw,
    const float* __restrict__ lnb, float* __restrict__ out, int nrows) {
    extern __shared__ float sm[];
    float* A   = sm;                   // [TR][PROW]  x, later xtp
    float* XL  = A + TR * PROW;        // [TR][PROW]  parked xl (thread-local slots)
    float* CW  = XL + TR * PROW;       // 324 padded dense w3j
    float* RED = CW + 324;             // 48 q + 16 s1

    const int tid = threadIdx.x;
    const int rowbase = blockIdx.x * TR;
    const float S = 0.08838834764831845f;   // 1/sqrt(128)
    const float C3 = 0.57735026918962576f;  // 1/sqrt(3)
    const float C5 = 0.44721359549995794f;  // 1/sqrt(5)
    const float PW0 = 0.5773502691896258f;  // sqrt(1/3)
    const float PW1 = 0.8660254037844386f;  // sqrt(3/4)
    const float PW2 = 1.1180339887498949f;  // sqrt(5/4)

    // padded CW: T112 @0 [3][3][z6], T121 @54 [3][5][z4], T211 @114 [5][3][z4], T222 @174 [5][5][z6]
    for (int i = tid; i < 45; i += NT) {
        int xx = i / 15, yy = (i % 15) / 5, zz = i % 5;
        CW[(xx * 3 + yy) * 6 + zz] = g_w3j[53 + i];
    }
    for (int i = tid; i < 45; i += NT) {
        int xx = i / 15, yy = (i % 15) / 3, zz = i % 3;
        CW[54 + (xx * 5 + yy) * 4 + zz] = g_w3j[98 + i];
    }
    for (int i = tid; i < 45; i += NT) {
        int xx = i / 9, yy = (i % 9) / 3, zz = i % 3;
        CW[114 + (xx * 3 + yy) * 4 + zz] = g_w3j[168 + i];
    }
    for (int i = tid; i < 125; i += NT) {
        int xx = i / 25, yy = (i % 25) / 5, zz = i % 5;
        CW[174 + (xx * 5 + yy) * 6 + zz] = g_w3j[238 + i];
    }

    // load x -> padded smem (with dup slots)
    for (int r = 0; r < TR; r++) {
        int row = rowbase + r;
        const float* xrow = x + (size_t)row * ROWLEN;
        bool ok = row < nrows;
        float* Ar = A + r * PROW;
        for (int e = tid; e < ROWLEN; e += NT) {
            float v = ok ? __ldg(xrow + e) : 0.f;
            if (e < 128) {
                Ar[e] = v;
            } else if (e < 512) {
                int t = e - 128;
                int p = 128 + (t / 3) * 4 + (t % 3);
                Ar[p] = v;
                if ((t % 3) == 2) Ar[p + 1] = v;
            } else {
                int t = e - 512;
                int p = 640 + (t / 5) * 8 + (t % 5);
                Ar[p] = v;
                if ((t % 5) == 4) Ar[p + 1] = v;
            }
        }
    }
    __syncthreads();

    // ---- Fused linear L+R pass: one read of A serves both weight matrices.
    //      xl -> XL smem immediately per l-block; xr stays in registers. ----
    float xr0[TR];
    float xr1[TR][3];
    float xr2[TR][5];

    // l=0
    {
        float aL[TR] = {0, 0, 0, 0}, aR[TR] = {0, 0, 0, 0};
#pragma unroll 2
        for (int g = 0; g < 128; g += 4) {
            float wl[4], wr[4];
#pragma unroll
            for (int k = 0; k < 4; k++) {
                wl[k] = __ldg(lw + (g + k) * 128 + tid);
                wr[k] = __ldg(rw + (g + k) * 128 + tid);
            }
#pragma unroll
            for (int r = 0; r < TR; r++) {
                U4 xq; xq.q = *reinterpret_cast<const float4*>(&A[r * PROW + g]);
#pragma unroll
                for (int k = 0; k < 4; k++) {
                    aL[r] = fmaf(xq.f[k], wl[k], aL[r]);
                    aR[r] = fmaf(xq.f[k], wr[k], aR[r]);
                }
            }
        }
        float bl = __ldg(lb + tid), br = __ldg(rb + tid);
#pragma unroll
        for (int r = 0; r < TR; r++) {
            XL[r * PROW + tid] = aL[r] * S + bl;
            xr0[r] = aR[r] * S + br;
        }
    }

    // l=1
    {
        unsigned long long pL[TR] = {0,0,0,0}, pR[TR] = {0,0,0,0}, sLR[TR] = {0,0,0,0};
        const float* WL = lw + 16384;
        const float* WR = rw + 16384;
#pragma unroll 2
        for (int g = 0; g < 128; g += 4) {
            float wl[4], wr[4];
#pragma unroll
            for (int k = 0; k < 4; k++) {
                wl[k] = __ldg(WL + (g + k) * 128 + tid);
                wr[k] = __ldg(WR + (g + k) * 128 + tid);
            }
#pragma unroll
            for (int k = 0; k < 4; k++) {
                unsigned long long wl2 = pack2f(wl[k], wl[k]);
                unsigned long long wr2 = pack2f(wr[k], wr[k]);
                unsigned long long wlr = pack2f(wl[k], wr[k]);
#pragma unroll
                for (int r = 0; r < TR; r++) {
                    U4 q; q.q = *reinterpret_cast<const float4*>(
                        &A[r * PROW + 128 + (g + k) * 4]);
                    ffma2(pL[r], q.p[0], wl2);
                    ffma2(pR[r], q.p[0], wr2);
                    ffma2(sLR[r], q.p[1], wlr);   // lanes: (c2*wl, c2*wr)
                }
            }
        }
#pragma unroll
        for (int r = 0; r < TR; r++) {
            float2 t = unpack2(pL[r]);
            float2 s = unpack2(sLR[r]);
            float xl3 = s.x * S;
            *reinterpret_cast<float4*>(&XL[r * PROW + 128 + tid * 4]) =
                make_float4(t.x * S, t.y * S, xl3, xl3);
            t = unpack2(pR[r]);
            xr1[r][0] = t.x * S; xr1[r][1] = t.y * S; xr1[r][2] = s.y * S;
        }
    }

    // l=2
    {
        unsigned long long pL0[TR] = {0,0,0,0}, pL1[TR] = {0,0,0,0};
        unsigned long long pR0[TR] = {0,0,0,0}, pR1[TR] = {0,0,0,0};
        unsigned long long sLR[TR] = {0,0,0,0};
        const float* WL = lw + 32768;
        const float* WR = rw + 32768;
#pragma unroll 2
        for (int g = 0; g < 128; g += 4) {
            float wl[4], wr[4];
#pragma unroll
            for (int k = 0; k < 4; k++) {
                wl[k] = __ldg(WL + (g + k) * 128 + tid);
                wr[k] = __ldg(WR + (g + k) * 128 + tid);
            }
#pragma unroll
            for (int k = 0; k < 4; k++) {
                unsigned long long wl2 = pack2f(wl[k], wl[k]);
                unsigned long long wr2 = pack2f(wr[k], wr[k]);
                unsigned long long wlr = pack2f(wl[k], wr[k]);
#pragma unroll
                for (int r = 0; r < TR; r++) {
                    const float* base = &A[r * PROW + 640 + (g + k) * 8];
                    U4 q; q.q = *reinterpret_cast<const float4*>(base);
                    U2 d; d.q = *reinterpret_cast<const float2*>(base + 4);  // (c4, c4)
                    ffma2(pL0[r], q.p[0], wl2);
                    ffma2(pL1[r], q.p[1], wl2);
                    ffma2(pR0[r], q.p[0], wr2);
                    ffma2(pR1[r], q.p[1], wr2);
                    ffma2(sLR[r], d.p, wlr);      // lanes: (c4*wl, c4*wr)
                }
            }
        }
#pragma unroll
        for (int r = 0; r < TR; r++) {
            float2 a = unpack2(pL0[r]);
            float2 b = unpack2(pL1[r]);
            float2 s = unpack2(sLR[r]);
            float xl8 = s.x * S;
            *reinterpret_cast<float4*>(&XL[r * PROW + 640 + tid * 8]) =
                make_float4(a.x * S, a.y * S, b.x * S, b.y * S);
            *reinterpret_cast<float2*>(&XL[r * PROW + 640 + tid * 8 + 4]) =
                make_float2(xl8, xl8);
            a = unpack2(pR0[r]);
            b = unpack2(pR1[r]);
            xr2[r][0] = a.x * S; xr2[r][1] = a.y * S;
            xr2[r][2] = b.x * S; xr2[r][3] = b.y * S; xr2[r][4] = s.y * S;
        }
    }

    __syncthreads();  // all warps done reading A before xtp overwrite

    // ---- tensor product: xl from XL smem (own slots), xr from regs -> xtp into A ----
    {
        float tw[11];
#pragma unroll
        for (int n = 0; n < 11; n++) tw[n] = __ldg(tpw + n * 128 + tid);
        float f00  = PW0 * tw[0];
        float f0d1 = PW0 * C3 * tw[4];
        float f0d2 = PW0 * C5 * tw[9];
        float f1a  = PW1 * C3 * tw[1];
        float f1b  = PW1 * C3 * tw[3];
        float f2a  = PW2 * C5 * tw[2];
        float f2b  = PW2 * C5 * tw[7];
        float f112 = PW2 * tw[5];
        float f121 = PW1 * tw[6];
        float f211 = PW1 * tw[8];
        float f222 = PW2 * tw[10];
#pragma unroll
        for (int r = 0; r < TR; r++) {
            const float* Xr = XL + r * PROW;
            float cl[9];
            cl[0] = Xr[tid];
            {
                U4 q; q.q = *reinterpret_cast<const float4*>(&Xr[128 + tid * 4]);
                cl[1] = q.f[0]; cl[2] = q.f[1]; cl[3] = q.f[2];
            }
            {
                U4 q; q.q = *reinterpret_cast<const float4*>(&Xr[640 + tid * 8]);
                cl[4] = q.f[0]; cl[5] = q.f[1]; cl[6] = q.f[2]; cl[7] = q.f[3];
                cl[8] = Xr[640 + tid * 8 + 4];
            }
            float cr[9];
            cr[0] = xr0[r];
            cr[1] = xr1[r][0]; cr[2] = xr1[r][1]; cr[3] = xr1[r][2];
            cr[4] = xr2[r][0]; cr[5] = xr2[r][1]; cr[6] = xr2[r][2];
            cr[7] = xr2[r][3]; cr[8] = xr2[r][4];

            float o[9];
            float t0 = f00 * cl[0] * cr[0];
            float d1 = cl[1] * cr[1] + cl[2] * cr[2] + cl[3] * cr[3];
            t0 = fmaf(f0d1, d1, t0);
            float d2 = cl[4] * cr[4] + cl[5] * cr[5] + cl[6] * cr[6] +
                       cl[7] * cr[7] + cl[8] * cr[8];
            t0 = fmaf(f0d2, d2, t0);
            o[0] = t0;
#pragma unroll
            for (int z = 0; z < 3; z++)
                o[1 + z] = f1a * cl[0] * cr[1 + z] + f1b * cl[1 + z] * cr[0];
#pragma unroll
            for (int z = 0; z < 5; z++)
                o[4 + z] = f2a * cl[0] * cr[4 + z] + f2b * cl[4 + z] * cr[0];
            tp_z6<3, 3>(CW,       cl + 1, cr + 1, o + 4, f112);
            tp_z4<3, 5>(CW + 54,  cl + 1, cr + 4, o + 1, f121);
            tp_z4<5, 3>(CW + 114, cl + 4, cr + 1, o + 1, f211);
            tp_z6<5, 5>(CW + 174, cl + 4, cr + 4, o + 4, f222);

            float* Ar = A + r * PROW;
            Ar[tid] = o[0];
            *reinterpret_cast<float4*>(&Ar[128 + tid * 4]) =
                make_float4(o[1], o[2], o[3], o[3]);
            *reinterpret_cast<float4*>(&Ar[640 + tid * 8]) =
                make_float4(o[4], o[5], o[6], o[7]);
            *reinterpret_cast<float2*>(&Ar[640 + tid * 8 + 4]) =
                make_float2(o[8], o[8]);
        }
    }
    __syncthreads();

    // ---- linear P -> fii in registers ----
    float fii[TR][9];
    linear_pass(pwm, A, fii, tid);
    {
        float bb = __ldg(pb + tid);
#pragma unroll
        for (int r = 0; r < TR; r++) fii[r][0] += bb;
    }

    // ---- stats ----
#pragma unroll
    for (int r = 0; r < TR; r++) {
        float c0 = fii[r][0];
        float q0 = c0 * c0;
        float s1 = c0;
        float q1 = fii[r][1] * fii[r][1] + fii[r][2] * fii[r][2] + fii[r][3] * fii[r][3];
        float q2 = fii[r][4] * fii[r][4] + fii[r][5] * fii[r][5] + fii[r][6] * fii[r][6] +
                   fii[r][7] * fii[r][7] + fii[r][8] * fii[r][8];
#pragma unroll
        for (int off = 16; off; off >>= 1) {
            q0 += __shfl_xor_sync(0xffffffffu, q0, off);
            s1 += __shfl_xor_sync(0xffffffffu, s1, off);
            q1 += __shfl_xor_sync(0xffffffffu, q1, off);
            q2 += __shfl_xor_sync(0xffffffffu, q2, off);
        }
        if ((tid & 31) == 0) {
            int w = tid >> 5;
            RED[(r * 3 + 0) * 4 + w] = q0;
            RED[(r * 3 + 1) * 4 + w] = q1;
            RED[(r * 3 + 2) * 4 + w] = q2;
            RED[48 + r * 4 + w] = s1;
        }
    }
    __syncthreads();

    float mu[TR], inv0[TR], inv1[TR], inv2[TR];
#pragma unroll
    for (int r = 0; r < TR; r++) {
        float s1 = RED[48 + r * 4 + 0] + RED[48 + r * 4 + 1] +
                   RED[48 + r * 4 + 2] + RED[48 + r * 4 + 3];
        mu[r] = s1 * (1.f / 128.f);
        float q0 = RED[(r * 3 + 0) * 4 + 0] + RED[(r * 3 + 0) * 4 + 1] +
                   RED[(r * 3 + 0) * 4 + 2] + RED[(r * 3 + 0) * 4 + 3];
        float q1 = RED[(r * 3 + 1) * 4 + 0] + RED[(r * 3 + 1) * 4 + 1] +
                   RED[(r * 3 + 1) * 4 + 2] + RED[(r * 3 + 1) * 4 + 3];
        float q2 = RED[(r * 3 + 2) * 4 + 0] + RED[(r * 3 + 2) * 4 + 1] +
                   RED[(r * 3 + 2) * 4 + 2] + RED[(r * 3 + 2) * 4 + 3];
        float fn0 = q0 * (1.f / 128.f) - mu[r] * mu[r];
        inv0[r] = rsqrtf(fn0 + 1e-5f);
        inv1[r] = rsqrtf(q1 * (1.f / 384.f) + 1e-5f);
        inv2[r] = rsqrtf(q2 * (1.f / 640.f) + 1e-5f);
    }

    // ---- normalize + residual + store ----
    float w0 = __ldg(lnw + tid), w1 = __ldg(lnw + 128 + tid), w2 = __ldg(lnw + 256 + tid);
    float b0 = __ldg(lnb + tid);
#pragma unroll
    for (int r = 0; r < TR; r++) {
        int row = rowbase + r;
        if (row >= nrows) continue;
        size_t gb = (size_t)row * ROWLEN;
        out[gb + tid] = (fii[r][0] - mu[r]) * inv0[r] * w0 + b0 + __ldg(oldf + gb + tid);
#pragma unroll
        for (int i = 0; i < 3; i++) {
            size_t e = gb + 128 + tid * 3 + i;
            out[e] = fii[r][1 + i] * inv1[r] * w1 + __ldg(oldf + e);
        }
#pragma unroll
        for (int i = 0; i < 5; i++) {
            size_t e = gb + 512 + tid * 5 + i;
            out[e] = fii[r][4 + i] * inv2[r] * w2 + __ldg(oldf + e);
        }
    }
}

// ---------------------------------------------------------------------------
extern "C" void kernel_launch(void* const* d_in, const int* in_sizes, int n_in,
                              void* d_out, int out_size) {
    const float* x    = (const float*)d_in[0];
    const float* oldf = (const float*)d_in[1];
    const float* lw   = (const float*)d_in[2];
    const float* lb   = (const float*)d_in[3];
    const float* rw   = (const float*)d_in[4];
    const float* rb   = (const float*)d_in[5];
    const float* pwm  = (const float*)d_in[6];
    const float* pb   = (const float*)d_in[7];
    const float* tpw  = (const float*)d_in[8];
    const float* lnw  = (const float*)d_in[9];
    const float* lnb  = (const float*)d_in[10];
    float* out = (float*)d_out;

    int nrows = in_sizes[0] / ROWLEN;
    const int smem_bytes = (2 * TR * PROW + 324 + 64) * sizeof(float);  // 54800 B

    cudaFuncSetAttribute(self_layer_kernel,
                         cudaFuncAttributeMaxDynamicSharedMemorySize, smem_bytes);

    w3j_init_kernel<<<1, 32>>>();

    int grid = (nrows + TR - 1) / TR;
    self_layer_kernel<<<grid, NT, smem_bytes>>>(x, oldf, lw, lb, rw, rb, pwm, pb,
                                                tpw, lnw, lnb, out, nrows);
}

// round 13
// speedup vs baseline: 1.0253x; 1.0253x over previous
#include <cuda_runtime.h>
#include <math.h>

#define ROWLEN 1152
#define PROW   1664   // padded row: l0 [0,128) | l1 @128 stride4 (slot3=dup c2) | l2 @640 stride8 (slot5=dup c4)
#define TR     5
#define NT     128

// ---------------------------------------------------------------------------
// Wigner-3j (real basis, e3nn phase convention) computed on device at launch.
// ---------------------------------------------------------------------------
__device__ float g_w3j[363];

__device__ __forceinline__ double dfact(int n) {
    double r = 1.0;
    for (int i = 2; i <= n; i++) r *= (double)i;
    return r;
}

__device__ double cg_racah(int j1, int m1, int j2, int m2, int j3, int m3) {
    if (m1 + m2 != m3) return 0.0;
    double pre = sqrt((2.0 * j3 + 1.0) * dfact(j3 + j1 - j2) * dfact(j3 - j1 + j2) *
                      dfact(j1 + j2 - j3) / dfact(j1 + j2 + j3 + 1));
    pre *= sqrt(dfact(j3 + m3) * dfact(j3 - m3) * dfact(j1 - m1) * dfact(j1 + m1) *
                dfact(j2 - m2) * dfact(j2 + m2));
    double s = 0.0;
    for (int k = 0; k <= j1 + j2 - j3; k++) {
        int d0 = k, d1 = j1 + j2 - j3 - k, d2 = j1 - m1 - k, d3 = j2 + m2 - k;
        int d4 = j3 - j2 + m1 + k, d5 = j3 - j1 - m2 + k;
        if (d0 < 0 || d1 < 0 || d2 < 0 || d3 < 0 || d4 < 0 || d5 < 0) continue;
        s += ((k & 1) ? -1.0 : 1.0) /
             (dfact(d0) * dfact(d1) * dfact(d2) * dfact(d3) * dfact(d4) * dfact(d5));
    }
    return pre * s;
}

__device__ int qrow(int l, int x, int* col, double* qre, double* qim) {
    const double s = 0.70710678118654752440;
    if (x == l) { col[0] = l; qre[0] = 1.0; qim[0] = 0.0; return 1; }
    if (x > l) {
        int m = x - l;
        col[0] = l - m; qre[0] = s;                 qim[0] = 0.0;
        col[1] = l + m; qre[1] = (m & 1) ? -s : s;  qim[1] = 0.0;
        return 2;
    }
    int m = l - x;
    col[0] = l - m; qre[0] = 0.0; qim[0] = s;
    col[1] = l + m; qre[1] = 0.0; qim[1] = (m & 1) ? s : -s;
    return 2;
}

__global__ void w3j_init_kernel() {
    __shared__ double WS[11][384];
    int t = threadIdx.x;
    if (t >= 11) return;
    const int L1[11] = {0,0,0,1,1,1,1,2,2,2,2};
    const int L2[11] = {0,1,2,0,1,1,2,0,1,2,2};
    const int L3[11] = {0,1,2,1,0,2,1,2,1,0,2};
    const int OFF[11] = {0,1,10,35,44,53,98,143,168,213,238};
    int l1 = L1[t], l2 = L2[t], l3 = L3[t];
    int d1 = 2*l1+1, d2 = 2*l2+1, d3 = 2*l3+1;
    double* Wc  = WS[t];
    double* Wre = Wc + 125;
    double* Wim = Wre + 125;
    for (int i = 0; i < 125; i++) Wc[i] = 0.0;

    for (int m1 = -l1; m1 <= l1; m1++)
        for (int m2 = -l2; m2 <= l2; m2++) {
            int m3 = -(m1 + m2);
            if (m3 < -l3 || m3 > l3) continue;
            int e = l1 - l2 - m3;
            double par = (((e % 2) + 2) % 2) ? -1.0 : 1.0;
            Wc[((m1 + l1) * d2 + (m2 + l2)) * d3 + (m3 + l3)] =
                par / sqrt(2.0 * l3 + 1.0) * cg_racah(l1, m1, l2, m2, l3, -m3);
        }

    for (int x = 0; x < d1; x++) {
        int ca[2]; double ar[2], ai[2]; int na = qrow(l1, x, ca, ar, ai);
        for (int y = 0; y < d2; y++) {
            int cb[2]; double br[2], bi[2]; int nb = qrow(l2, y, cb, br, bi);
            for (int z = 0; z < d3; z++) {
                int cc[2]; double cr[2], ci[2]; int nc = qrow(l3, z, cc, cr, ci);
                double sr = 0.0, si = 0.0;
                for (int ia = 0; ia < na; ia++)
                    for (int ib = 0; ib < nb; ib++) {
                        double pre = ar[ia]*br[ib] - ai[ia]*bi[ib];
                        double pim = ar[ia]*bi[ib] + ai[ia]*br[ib];
                        for (int ic = 0; ic < nc; ic++) {
                            double wc = Wc[(ca[ia]*d2 + cb[ib])*d3 + cc[ic]];
                            if (wc == 0.0) continue;
                            double qre = pre*cr[ic] - pim*ci[ic];
                            double qim = pre*ci[ic] + pim*cr[ic];
                            sr += qre * wc;
                            si += qim * wc;
                        }
                    }
                Wre[(x*d2 + y)*d3 + z] = sr;
                Wim[(x*d2 + y)*d3 + z] = si;
            }
        }
    }

    // Phase normalization. (2,2,2): numpy argmax tie-break lands on d0^3 (flat 62).
    int n = d1 * d2 * d3;
    int idx;
    if (l1 == 2 && l2 == 2 && l3 == 2) {
        idx = (2 * d2 + 2) * d3 + 2;
    } else {
        double M = 0.0;
        for (int i = 0; i < n; i++) {
            double h = sqrt(Wre[i]*Wre[i] + Wim[i]*Wim[i]);
            if (h > M) M = h;
        }
        idx = 0;
        for (int i = 0; i < n; i++) {
            double h = sqrt(Wre[i]*Wre[i] + Wim[i]*Wim[i]);
            if (h >= M * (1.0 - 1e-9)) { idx = i; break; }
        }
    }
    double h = sqrt(Wre[idx]*Wre[idx] + Wim[idx]*Wim[idx]);
    double pr = Wre[idx] / h, pi = Wim[idx] / h;
    for (int i = 0; i < n; i++)
        g_w3j[OFF[t] + i] = (float)(Wre[i]*pr + Wim[i]*pi);
}

// ---------------------------------------------------------------------------
// f32x2 helpers
// ---------------------------------------------------------------------------
__device__ __forceinline__ unsigned long long pack2f(float lo, float hi) {
    unsigned long long r;
    asm("mov.b64 %0, {%1, %2};" : "=l"(r) : "f"(lo), "f"(hi));
    return r;
}
__device__ __forceinline__ void ffma2(unsigned long long& d, unsigned long long a,
                                      unsigned long long b) {
    asm("fma.rn.f32x2 %0, %1, %2, %0;" : "+l"(d) : "l"(a), "l"(b));
}
__device__ __forceinline__ float2 unpack2(unsigned long long p) {
    float2 r;
    asm("mov.b64 {%0, %1}, %2;" : "=f"(r.x), "=f"(r.y) : "l"(p));
    return r;
}
union U4 { float4 q; unsigned long long p[2]; float f[4]; };
union U2 { float2 q; unsigned long long p; float f[2]; };

// Dense TP contraction, W stored with z-stride 6 (dk=5, pairs (0,1),(2,3), scalar 4).
template <int DI, int DJ>
__device__ __forceinline__ void tp_z6(const float* W, const float* cl,
                                      const float* cr, float* o, float f) {
    unsigned long long p01 = 0, p23 = 0;
    float t4 = 0.f;
#pragma unroll
    for (int x = 0; x < DI; x++)
#pragma unroll
        for (int y = 0; y < DJ; y++) {
            float pr = cl[x] * cr[y];
            unsigned long long pp = pack2f(pr, pr);
            const float* wb = W + (x * DJ + y) * 6;
            U2 w01, w23;
            w01.q = *reinterpret_cast<const float2*>(wb);
            w23.q = *reinterpret_cast<const float2*>(wb + 2);
            float w4 = wb[4];
            ffma2(p01, pp, w01.p);
            ffma2(p23, pp, w23.p);
            t4 = fmaf(pr, w4, t4);
        }
    float2 a = unpack2(p01), b = unpack2(p23);
    o[0] = fmaf(f, a.x, o[0]);
    o[1] = fmaf(f, a.y, o[1]);
    o[2] = fmaf(f, b.x, o[2]);
    o[3] = fmaf(f, b.y, o[3]);
    o[4] = fmaf(f, t4, o[4]);
}

// Dense TP contraction, W stored with z-stride 4 (dk=3, pair (0,1), scalar 2).
template <int DI, int DJ>
__device__ __forceinline__ void tp_z4(const float* W, const float* cl,
                                      const float* cr, float* o, float f) {
    unsigned long long p01 = 0;
    float t2 = 0.f;
#pragma unroll
    for (int x = 0; x < DI; x++)
#pragma unroll
        for (int y = 0; y < DJ; y++) {
            float pr = cl[x] * cr[y];
            unsigned long long pp = pack2f(pr, pr);
            const float* wb = W + (x * DJ + y) * 4;
            U2 w01;
            w01.q = *reinterpret_cast<const float2*>(wb);
            float w2 = wb[2];
            ffma2(p01, pp, w01.p);
            t2 = fmaf(pr, w2, t2);
        }
    float2 a = unpack2(p01);
    o[0] = fmaf(f, a.x, o[0]);
    o[1] = fmaf(f, a.y, o[1]);
    o[2] = fmaf(f, t2, o[2]);
}

// One-operand linear pass over A (padded layout) producing y[TR][9]. Used for linP.
__device__ __forceinline__ void linear_pass(const float* __restrict__ W,
                                            const float* A, float y[TR][9],
                                            int tid) {
    const float S = 0.08838834764831845f;  // 1/sqrt(128)
    // l=0
    {
        float a0[TR];
#pragma unroll
        for (int r = 0; r < TR; r++) a0[r] = 0.f;
#pragma unroll 2
        for (int g = 0; g < 128; g += 4) {
            float w[4];
#pragma unroll
            for (int k = 0; k < 4; k++) w[k] = __ldg(W + (g + k) * 128 + tid);
#pragma unroll
            for (int r = 0; r < TR; r++) {
                U4 xq; xq.q = *reinterpret_cast<const float4*>(&A[r * PROW + g]);
#pragma unroll
                for (int k = 0; k < 4; k++) a0[r] = fmaf(xq.f[k], w[k], a0[r]);
            }
        }
#pragma unroll
        for (int r = 0; r < TR; r++) y[r][0] = a0[r] * S;
    }
    // l=1
    {
        unsigned long long p01[TR], s2[TR];
#pragma unroll
        for (int r = 0; r < TR; r++) { p01[r] = 0; s2[r] = 0; }
        const float* Wl = W + 16384;
#pragma unroll 2
        for (int g = 0; g < 128; g += 4) {
            float w[4];
#pragma unroll
            for (int k = 0; k < 4; k++) w[k] = __ldg(Wl + (g + k) * 128 + tid);
#pragma unroll
            for (int k = 0; k < 4; k++) {
                unsigned long long w2 = pack2f(w[k], w[k]);
#pragma unroll
                for (int r = 0; r < TR; r++) {
                    U4 q; q.q = *reinterpret_cast<const float4*>(
                        &A[r * PROW + 128 + (g + k) * 4]);
                    ffma2(p01[r], q.p[0], w2);
                    ffma2(s2[r], q.p[1], w2);   // both lanes accumulate c2*w
                }
            }
        }
#pragma unroll
        for (int r = 0; r < TR; r++) {
            float2 t = unpack2(p01[r]);
            y[r][1] = t.x * S; y[r][2] = t.y * S;
            y[r][3] = unpack2(s2[r]).x * S;
        }
    }
    // l=2
    {
        unsigned long long p0[TR], p1[TR], s4[TR];
#pragma unroll
        for (int r = 0; r < TR; r++) { p0[r] = 0; p1[r] = 0; s4[r] = 0; }
        const float* Wl = W + 32768;
#pragma unroll 2
        for (int g = 0; g < 128; g += 4) {
            float w[4];
#pragma unroll
            for (int k = 0; k < 4; k++) w[k] = __ldg(Wl + (g + k) * 128 + tid);
#pragma unroll
            for (int k = 0; k < 4; k++) {
                unsigned long long w2 = pack2f(w[k], w[k]);
#pragma unroll
                for (int r = 0; r < TR; r++) {
                    const float* base = &A[r * PROW + 640 + (g + k) * 8];
                    U4 q; q.q = *reinterpret_cast<const float4*>(base);
                    U2 d; d.q = *reinterpret_cast<const float2*>(base + 4);
                    ffma2(p0[r], q.p[0], w2);
                    ffma2(p1[r], q.p[1], w2);
                    ffma2(s4[r], d.p, w2);
                }
            }
        }
#pragma unroll
        for (int r = 0; r < TR; r++) {
            float2 t = unpack2(p0[r]);
            y[r][4] = t.x * S; y[r][5] = t.y * S;
            t = unpack2(p1[r]);
            y[r][6] = t.x * S; y[r][7] = t.y * S;
            y[r][8] = unpack2(s4[r]).x * S;
        }
    }
}

// ---------------------------------------------------------------------------
// Fused main kernel. TR=5, occ=3: 168 regs/thread available so the fused-L/R
// accumulators finally fit (kills the 1.5 TB/s spill traffic seen at
// TR=4/occ4), and 10000 CTAs instead of 12500 cuts weight-stream traffic 20%.
// ---------------------------------------------------------------------------
__global__ __launch_bounds__(NT, 3) void self_layer_kernel(
    const float* __restrict__ x, const float* __restrict__ oldf,
    const float* __restrict__ lw, const float* __restrict__ lb,
    const float* __restrict__ rw, const float* __restrict__ rb,
    const float* __restrict__ pwm, const float* __restrict__ pb,
    const float* __restrict__ tpw, const float* __restrict__ lnw,
    const float* __restrict__ lnb, float* __restrict__ out, int nrows) {
    extern __shared__ float sm[];
    float* A   = sm;                   // [TR][PROW]  x, later xtp
    float* XL  = A + TR * PROW;        // [TR][PROW]  parked xl (thread-local slots)
    float* CW  = XL + TR * PROW;       // 324 padded dense w3j
    float* RED = CW + 324;             // TR*3*4 q + TR*4 s1

    const int tid = threadIdx.x;
    const int rowbase = blockIdx.x * TR;
    const float S = 0.08838834764831845f;   // 1/sqrt(128)
    const float C3 = 0.57735026918962576f;  // 1/sqrt(3)
    const float C5 = 0.44721359549995794f;  // 1/sqrt(5)
    const float PW0 = 0.5773502691896258f;  // sqrt(1/3)
    const float PW1 = 0.8660254037844386f;  // sqrt(3/4)
    const float PW2 = 1.1180339887498949f;  // sqrt(5/4)

    // padded CW: T112 @0 [3][3][z6], T121 @54 [3][5][z4], T211 @114 [5][3][z4], T222 @174 [5][5][z6]
    for (int i = tid; i < 45; i += NT) {
        int xx = i / 15, yy = (i % 15) / 5, zz = i % 5;
        CW[(xx * 3 + yy) * 6 + zz] = g_w3j[53 + i];
    }
    for (int i = tid; i < 45; i += NT) {
        int xx = i / 15, yy = (i % 15) / 3, zz = i % 3;
        CW[54 + (xx * 5 + yy) * 4 + zz] = g_w3j[98 + i];
    }
    for (int i = tid; i < 45; i += NT) {
        int xx = i / 9, yy = (i % 9) / 3, zz = i % 3;
        CW[114 + (xx * 3 + yy) * 4 + zz] = g_w3j[168 + i];
    }
    for (int i = tid; i < 125; i += NT) {
        int xx = i / 25, yy = (i % 25) / 5, zz = i % 5;
        CW[174 + (xx * 5 + yy) * 6 + zz] = g_w3j[238 + i];
    }

    // load x -> padded smem (with dup slots)
    for (int r = 0; r < TR; r++) {
        int row = rowbase + r;
        const float* xrow = x + (size_t)row * ROWLEN;
        bool ok = row < nrows;
        float* Ar = A + r * PROW;
        for (int e = tid; e < ROWLEN; e += NT) {
            float v = ok ? __ldg(xrow + e) : 0.f;
            if (e < 128) {
                Ar[e] = v;
            } else if (e < 512) {
                int t = e - 128;
                int p = 128 + (t / 3) * 4 + (t % 3);
                Ar[p] = v;
                if ((t % 3) == 2) Ar[p + 1] = v;
            } else {
                int t = e - 512;
                int p = 640 + (t / 5) * 8 + (t % 5);
                Ar[p] = v;
                if ((t % 5) == 4) Ar[p + 1] = v;
            }
        }
    }
    __syncthreads();

    // ---- Fused linear L+R pass: one read of A serves both weight matrices.
    //      xl -> XL smem immediately per l-block; xr stays in registers. ----
    float xr0[TR];
    float xr1[TR][3];
    float xr2[TR][5];

    // l=0
    {
        float aL[TR], aR[TR];
#pragma unroll
        for (int r = 0; r < TR; r++) { aL[r] = 0.f; aR[r] = 0.f; }
#pragma unroll 2
        for (int g = 0; g < 128; g += 4) {
            float wl[4], wr[4];
#pragma unroll
            for (int k = 0; k < 4; k++) {
                wl[k] = __ldg(lw + (g + k) * 128 + tid);
                wr[k] = __ldg(rw + (g + k) * 128 + tid);
            }
#pragma unroll
            for (int r = 0; r < TR; r++) {
                U4 xq; xq.q = *reinterpret_cast<const float4*>(&A[r * PROW + g]);
#pragma unroll
                for (int k = 0; k < 4; k++) {
                    aL[r] = fmaf(xq.f[k], wl[k], aL[r]);
                    aR[r] = fmaf(xq.f[k], wr[k], aR[r]);
                }
            }
        }
        float bl = __ldg(lb + tid), br = __ldg(rb + tid);
#pragma unroll
        for (int r = 0; r < TR; r++) {
            XL[r * PROW + tid] = aL[r] * S + bl;
            xr0[r] = aR[r] * S + br;
        }
    }

    // l=1
    {
        unsigned long long pL[TR], pR[TR], sLR[TR];
#pragma unroll
        for (int r = 0; r < TR; r++) { pL[r] = 0; pR[r] = 0; sLR[r] = 0; }
        const float* WL = lw + 16384;
        const float* WR = rw + 16384;
#pragma unroll 2
        for (int g = 0; g < 128; g += 4) {
            float wl[4], wr[4];
#pragma unroll
            for (int k = 0; k < 4; k++) {
                wl[k] = __ldg(WL + (g + k) * 128 + tid);
                wr[k] = __ldg(WR + (g + k) * 128 + tid);
            }
#pragma unroll
            for (int k = 0; k < 4; k++) {
                unsigned long long wl2 = pack2f(wl[k], wl[k]);
                unsigned long long wr2 = pack2f(wr[k], wr[k]);
                unsigned long long wlr = pack2f(wl[k], wr[k]);
#pragma unroll
                for (int r = 0; r < TR; r++) {
                    U4 q; q.q = *reinterpret_cast<const float4*>(
                        &A[r * PROW + 128 + (g + k) * 4]);
                    ffma2(pL[r], q.p[0], wl2);
                    ffma2(pR[r], q.p[0], wr2);
                    ffma2(sLR[r], q.p[1], wlr);   // lanes: (c2*wl, c2*wr)
                }
            }
        }
#pragma unroll
        for (int r = 0; r < TR; r++) {
            float2 t = unpack2(pL[r]);
            float2 s = unpack2(sLR[r]);
            float xl3 = s.x * S;
            *reinterpret_cast<float4*>(&XL[r * PROW + 128 + tid * 4]) =
                make_float4(t.x * S, t.y * S, xl3, xl3);
            t = unpack2(pR[r]);
            xr1[r][0] = t.x * S; xr1[r][1] = t.y * S; xr1[r][2] = s.y * S;
        }
    }

    // l=2
    {
        unsigned long long pL0[TR], pL1[TR], pR0[TR], pR1[TR], sLR[TR];
#pragma unroll
        for (int r = 0; r < TR; r++) {
            pL0[r] = 0; pL1[r] = 0; pR0[r] = 0; pR1[r] = 0; sLR[r] = 0;
        }
        const float* WL = lw + 32768;
        const float* WR = rw + 32768;
#pragma unroll 2
        for (int g = 0; g < 128; g += 4) {
            float wl[4], wr[4];
#pragma unroll
            for (int k = 0; k < 4; k++) {
                wl[k] = __ldg(WL + (g + k) * 128 + tid);
                wr[k] = __ldg(WR + (g + k) * 128 + tid);
            }
#pragma unroll
            for (int k = 0; k < 4; k++) {
                unsigned long long wl2 = pack2f(wl[k], wl[k]);
                unsigned long long wr2 = pack2f(wr[k], wr[k]);
                unsigned long long wlr = pack2f(wl[k], wr[k]);
#pragma unroll
                for (int r = 0; r < TR; r++) {
                    const float* base = &A[r * PROW + 640 + (g + k) * 8];
                    U4 q; q.q = *reinterpret_cast<const float4*>(base);
                    U2 d; d.q = *reinterpret_cast<const float2*>(base + 4);  // (c4, c4)
                    ffma2(pL0[r], q.p[0], wl2);
                    ffma2(pL1[r], q.p[1], wl2);
                    ffma2(pR0[r], q.p[0], wr2);
                    ffma2(pR1[r], q.p[1], wr2);
                    ffma2(sLR[r], d.p, wlr);      // lanes: (c4*wl, c4*wr)
                }
            }
        }
#pragma unroll
        for (int r = 0; r < TR; r++) {
            float2 a = unpack2(pL0[r]);
            float2 b = unpack2(pL1[r]);
            float2 s = unpack2(sLR[r]);
            float xl8 = s.x * S;
            *reinterpret_cast<float4*>(&XL[r * PROW + 640 + tid * 8]) =
                make_float4(a.x * S, a.y * S, b.x * S, b.y * S);
            *reinterpret_cast<float2*>(&XL[r * PROW + 640 + tid * 8 + 4]) =
                make_float2(xl8, xl8);
            a = unpack2(pR0[r]);
            b = unpack2(pR1[r]);
            xr2[r][0] = a.x * S; xr2[r][1] = a.y * S;
            xr2[r][2] = b.x * S; xr2[r][3] = b.y * S; xr2[r][4] = s.y * S;
        }
    }

    __syncthreads();  // all warps done reading A before xtp overwrite

    // ---- tensor product: xl from XL smem (own slots), xr from regs -> xtp into A ----
    {
        float tw[11];
#pragma unroll
        for (int n = 0; n < 11; n++) tw[n] = __ldg(tpw + n * 128 + tid);
        float f00  = PW0 * tw[0];
        float f0d1 = PW0 * C3 * tw[4];
        float f0d2 = PW0 * C5 * tw[9];
        float f1a  = PW1 * C3 * tw[1];
        float f1b  = PW1 * C3 * tw[3];
        float f2a  = PW2 * C5 * tw[2];
        float f2b  = PW2 * C5 * tw[7];
        float f112 = PW2 * tw[5];
        float f121 = PW1 * tw[6];
        float f211 = PW1 * tw[8];
        float f222 = PW2 * tw[10];
#pragma unroll
        for (int r = 0; r < TR; r++) {
            const float* Xr = XL + r * PROW;
            float cl[9];
            cl[0] = Xr[tid];
            {
                U4 q; q.q = *reinterpret_cast<const float4*>(&Xr[128 + tid * 4]);
                cl[1] = q.f[0]; cl[2] = q.f[1]; cl[3] = q.f[2];
            }
            {
                U4 q; q.q = *reinterpret_cast<const float4*>(&Xr[640 + tid * 8]);
                cl[4] = q.f[0]; cl[5] = q.f[1]; cl[6] = q.f[2]; cl[7] = q.f[3];
                cl[8] = Xr[640 + tid * 8 + 4];
            }
            float cr[9];
            cr[0] = xr0[r];
            cr[1] = xr1[r][0]; cr[2] = xr1[r][1]; cr[3] = xr1[r][2];
            cr[4] = xr2[r][0]; cr[5] = xr2[r][1]; cr[6] = xr2[r][2];
            cr[7] = xr2[r][3]; cr[8] = xr2[r][4];

            float o[9];
            float t0 = f00 * cl[0] * cr[0];
            float d1 = cl[1] * cr[1] + cl[2] * cr[2] + cl[3] * cr[3];
            t0 = fmaf(f0d1, d1, t0);
            float d2 = cl[4] * cr[4] + cl[5] * cr[5] + cl[6] * cr[6] +
                       cl[7] * cr[7] + cl[8] * cr[8];
            t0 = fmaf(f0d2, d2, t0);
            o[0] = t0;
#pragma unroll
            for (int z = 0; z < 3; z++)
                o[1 + z] = f1a * cl[0] * cr[1 + z] + f1b * cl[1 + z] * cr[0];
#pragma unroll
            for (int z = 0; z < 5; z++)
                o[4 + z] = f2a * cl[0] * cr[4 + z] + f2b * cl[4 + z] * cr[0];
            tp_z6<3, 3>(CW,       cl + 1, cr + 1, o + 4, f112);
            tp_z4<3, 5>(CW + 54,  cl + 1, cr + 4, o + 1, f121);
            tp_z4<5, 3>(CW + 114, cl + 4, cr + 1, o + 1, f211);
            tp_z6<5, 5>(CW + 174, cl + 4, cr + 4, o + 4, f222);

            float* Ar = A + r * PROW;
            Ar[tid] = o[0];
            *reinterpret_cast<float4*>(&Ar[128 + tid * 4]) =
                make_float4(o[1], o[2], o[3], o[3]);
            *reinterpret_cast<float4*>(&Ar[640 + tid * 8]) =
                make_float4(o[4], o[5], o[6], o[7]);
            *reinterpret_cast<float2*>(&Ar[640 + tid * 8 + 4]) =
                make_float2(o[8], o[8]);
        }
    }
    __syncthreads();

    // ---- linear P -> fii in registers ----
    float fii[TR][9];
    linear_pass(pwm, A, fii, tid);
    {
        float bb = __ldg(pb + tid);
#pragma unroll
        for (int r = 0; r < TR; r++) fii[r][0] += bb;
    }

    // ---- stats ----
#pragma unroll
    for (int r = 0; r < TR; r++) {
        float c0 = fii[r][0];
        float q0 = c0 * c0;
        float s1 = c0;
        float q1 = fii[r][1] * fii[r][1] + fii[r][2] * fii[r][2] + fii[r][3] * fii[r][3];
        float q2 = fii[r][4] * fii[r][4] + fii[r][5] * fii[r][5] + fii[r][6] * fii[r][6] +
                   fii[r][7] * fii[r][7] + fii[r][8] * fii[r][8];
#pragma unroll
        for (int off = 16; off; off >>= 1) {
            q0 += __shfl_xor_sync(0xffffffffu, q0, off);
            s1 += __shfl_xor_sync(0xffffffffu, s1, off);
            q1 += __shfl_xor_sync(0xffffffffu, q1, off);
            q2 += __shfl_xor_sync(0xffffffffu, q2, off);
        }
        if ((tid & 31) == 0) {
            int w = tid >> 5;
            RED[(r * 3 + 0) * 4 + w] = q0;
            RED[(r * 3 + 1) * 4 + w] = q1;
            RED[(r * 3 + 2) * 4 + w] = q2;
            RED[TR * 12 + r * 4 + w] = s1;
        }
    }
    __syncthreads();

    float mu[TR], inv0[TR], inv1[TR], inv2[TR];
#pragma unroll
    for (int r = 0; r < TR; r++) {
        float s1 = RED[TR * 12 + r * 4 + 0] + RED[TR * 12 + r * 4 + 1] +
                   RED[TR * 12 + r * 4 + 2] + RED[TR * 12 + r * 4 + 3];
        mu[r] = s1 * (1.f / 128.f);
        float q0 = RED[(r * 3 + 0) * 4 + 0] + RED[(r * 3 + 0) * 4 + 1] +
                   RED[(r * 3 + 0) * 4 + 2] + RED[(r * 3 + 0) * 4 + 3];
        float q1 = RED[(r * 3 + 1) * 4 + 0] + RED[(r * 3 + 1) * 4 + 1] +
                   RED[(r * 3 + 1) * 4 + 2] + RED[(r * 3 + 1) * 4 + 3];
        float q2 = RED[(r * 3 + 2) * 4 + 0] + RED[(r * 3 + 2) * 4 + 1] +
                   RED[(r * 3 + 2) * 4 + 2] + RED[(r * 3 + 2) * 4 + 3];
        float fn0 = q0 * (1.f / 128.f) - mu[r] * mu[r];
        inv0[r] = rsqrtf(fn0 + 1e-5f);
        inv1[r] = rsqrtf(q1 * (1.f / 384.f) + 1e-5f);
        inv2[r] = rsqrtf(q2 * (1.f / 640.f) + 1e-5f);
    }

    // ---- normalize + residual + store ----
    float w0 = __ldg(lnw + tid), w1 = __ldg(lnw + 128 + tid), w2 = __ldg(lnw + 256 + tid);
    float b0 = __ldg(lnb + tid);
#pragma unroll
    for (int r = 0; r < TR; r++) {
        int row = rowbase + r;
        if (row >= nrows) continue;
        size_t gb = (size_t)row * ROWLEN;
        out[gb + tid] = (fii[r][0] - mu[r]) * inv0[r] * w0 + b0 + __ldg(oldf + gb + tid);
#pragma unroll
        for (int i = 0; i < 3; i++) {
            size_t e = gb + 128 + tid * 3 + i;
            out[e] = fii[r][1 + i] * inv1[r] * w1 + __ldg(oldf + e);
        }
#pragma unroll
        for (int i = 0; i < 5; i++) {
            size_t e = gb + 512 + tid * 5 + i;
            out[e] = fii[r][4 + i] * inv2[r] * w2 + __ldg(oldf + e);
        }
    }
}

// ---------------------------------------------------------------------------
extern "C" void kernel_launch(void* const* d_in, const int* in_sizes, int n_in,
                              void* d_out, int out_size) {
    const float* x    = (const float*)d_in[0];
    const float* oldf = (const float*)d_in[1];
    const float* lw   = (const float*)d_in[2];
    const float* lb   = (const float*)d_in[3];
    const float* rw   = (const float*)d_in[4];
    const float* rb   = (const float*)d_in[5];
    const float* pwm  = (const float*)d_in[6];
    const float* pb   = (const float*)d_in[7];
    const float* tpw  = (const float*)d_in[8];
    const float* lnw  = (const float*)d_in[9];
    const float* lnb  = (const float*)d_in[10];
    float* out = (float*)d_out;

    int nrows = in_sizes[0] / ROWLEN;
    const int smem_bytes = (2 * TR * PROW + 324 + TR * 16 + 16) * sizeof(float);  // 68144 B

    cudaFuncSetAttribute(self_layer_kernel,
                         cudaFuncAttributeMaxDynamicSharedMemorySize, smem_bytes);

    w3j_init_kernel<<<1, 32>>>();

    int grid = (nrows + TR - 1) / TR;
    self_layer_kernel<<<grid, NT, smem_bytes>>>(x, oldf, lw, lb, rw, rb, pwm, pb,
                                                tpw, lnw, lnb, out, nrows);
}